// round 6
// baseline (speedup 1.0000x reference)
#include <cuda_runtime.h>
#include <cuda_bf16.h>
#include <cstdint>

#define N_VAR 4194304
#define M_CHK 2097152
#define DC 10
#define CBLK 256
#define ADJ_BYTES (CBLK * DC * 4)

// scratch (device globals: allocation-free)
__device__ float g_b0[N_VAR];
__device__ float g_b1[N_VAR];
__device__ float g_b2[N_VAR];

__device__ __forceinline__ uint32_t smem_u32(const void* p) {
    uint32_t a;
    asm("{ .reg .u64 t; cvta.to.shared.u64 t, %1; cvt.u32.u64 %0, t; }" : "=r"(a) : "l"(p));
    return a;
}

// seed accumulator: acc = scale*llr0 - v2c_prev  (scale = 1 mid, 2 for final/out)
// 2 float4 pairs per thread (4 independent loads in flight) for latency hiding.
#define SEED_T 256
#define SEED_ELEMS (N_VAR / 4)            // 1048576 float4 cells
#define SEED_STRIDE (SEED_ELEMS / 2)      // 524288
__global__ void __launch_bounds__(SEED_T) bp_seed(const float* __restrict__ llr0,
                                                  const float* __restrict__ v2c_prev,
                                                  float* __restrict__ acc, float scale) {
    int i = blockIdx.x * SEED_T + threadIdx.x;
    const float4* L = reinterpret_cast<const float4*>(llr0);
    const float4* P = reinterpret_cast<const float4*>(v2c_prev);
    float4* A = reinterpret_cast<float4*>(acc);

    float4 l0 = __ldcs(&L[i]);
    float4 p0 = __ldcs(&P[i]);
    float4 l1 = __ldcs(&L[i + SEED_STRIDE]);
    float4 p1 = __ldcs(&P[i + SEED_STRIDE]);

    float4 s0 = make_float4(fmaf(scale, l0.x, -p0.x), fmaf(scale, l0.y, -p0.y),
                            fmaf(scale, l0.z, -p0.z), fmaf(scale, l0.w, -p0.w));
    float4 s1 = make_float4(fmaf(scale, l1.x, -p1.x), fmaf(scale, l1.y, -p1.y),
                            fmaf(scale, l1.z, -p1.z), fmaf(scale, l1.w, -p1.w));
    A[i] = s0;
    A[i + SEED_STRIDE] = s1;
}

// check-node update: gather src (L2-only), min-sum, scatter-add into pre-seeded
// dst. adj rows staged to smem via TMA (keeps L1tex wavefronts for gathers/REDs).
__global__ void __launch_bounds__(CBLK) bp_check(const int* __restrict__ adj,
                                                 const float* __restrict__ gamma_p,
                                                 const float* __restrict__ src,
                                                 float* __restrict__ dst) {
    __shared__ __align__(16) int s_adj[CBLK * DC];
    __shared__ __align__(8) unsigned long long s_mbar;

    const int tid = threadIdx.x;
    uint32_t mbar = smem_u32(&s_mbar);
    uint32_t sdst = smem_u32(s_adj);

    if (tid == 0) {
        asm volatile("mbarrier.init.shared.b64 [%0], 1;" :: "r"(mbar) : "memory");
    }
    __syncthreads();
    if (tid == 0) {
        asm volatile("mbarrier.arrive.expect_tx.shared.b64 _, [%0], %1;"
                     :: "r"(mbar), "r"((uint32_t)ADJ_BYTES) : "memory");
        const int* gsrc = adj + (size_t)blockIdx.x * (CBLK * DC);
        asm volatile(
            "cp.async.bulk.shared::cta.global.mbarrier::complete_tx::bytes "
            "[%0], [%1], %2, [%3];"
            :: "r"(sdst), "l"(gsrc), "r"((uint32_t)ADJ_BYTES), "r"(mbar) : "memory");
    }
    // wait for TMA completion (phase 0)
    {
        uint32_t done;
        asm volatile(
            "{\n\t.reg .pred p;\n\t"
            "mbarrier.try_wait.parity.acquire.cta.shared::cta.b64 p, [%1], 0;\n\t"
            "selp.b32 %0, 1, 0, p;\n\t}"
            : "=r"(done) : "r"(mbar) : "memory");
        while (!done) {
            asm volatile(
                "{\n\t.reg .pred p;\n\t"
                "mbarrier.try_wait.parity.acquire.cta.shared::cta.b64 p, [%1], 0, 0x989680;\n\t"
                "selp.b32 %0, 1, 0, p;\n\t}"
                : "=r"(done) : "r"(mbar) : "memory");
        }
    }

    const float gamma = __ldg(gamma_p);
    const float vlast = __ldg(&src[N_VAR - 1]);  // all padded (-1) slots wrap here

    int idx[DC];
    #pragma unroll
    for (int j = 0; j < DC; j++) idx[j] = s_adj[tid * DC + j];

    float mag = __int_as_float(0x7f800000);  // +inf
    unsigned sgn = 0u;
    #pragma unroll
    for (int j = 0; j < DC; j++) {
        float v = (idx[j] >= 0) ? __ldcg(&src[idx[j]]) : vlast;
        sgn ^= (__float_as_uint(v + 1e-12f) & 0x80000000u);
        mag = fminf(mag, fabsf(v));
    }
    float c2v = __uint_as_float(__float_as_uint(gamma * mag) ^ sgn);

    #pragma unroll
    for (int j = 0; j < DC; j++) {
        if (idx[j] >= 0) atomicAdd(&dst[idx[j]], c2v);
    }
}

extern "C" void kernel_launch(void* const* d_in, const int* in_sizes, int n_in,
                              void* d_out, int out_size) {
    const float* llr0  = (const float*)d_in[0];
    const float* gamma = (const float*)d_in[1];
    const int*   adj   = (const int*)d_in[2];
    float* out = (float*)d_out;

    float *b0, *b1, *b2;
    cudaGetSymbolAddress((void**)&b0, g_b0);
    cudaGetSymbolAddress((void**)&b1, g_b1);
    cudaGetSymbolAddress((void**)&b2, g_b2);

    const int seed_blocks = SEED_STRIDE / SEED_T;   // 2048
    const int chk_blocks = M_CHK / CBLK;

    // n_iter = 5. Iter 1 is exact identity (v2c1 = llr0). Remaining 4 rounds:
    // accumulators pre-seeded with (llr0 - v2c_prev) so check's atomics produce
    // v2c_next in place; final accumulator is d_out seeded with (2*llr0 - v2c_4).
    cudaMemsetAsync(b0, 0, (size_t)N_VAR * sizeof(float));        // seed iter2: 0
    bp_check<<<chk_blocks, CBLK>>>(adj, gamma, llr0, b0);         // b0 = v2c_2
    bp_seed<<<seed_blocks, SEED_T>>>(llr0, b0, b1, 1.f);          // b1 = llr0 - v2c_2
    bp_check<<<chk_blocks, CBLK>>>(adj, gamma, b0, b1);           // b1 = v2c_3
    bp_seed<<<seed_blocks, SEED_T>>>(llr0, b1, b2, 1.f);          // b2 = llr0 - v2c_3
    bp_check<<<chk_blocks, CBLK>>>(adj, gamma, b1, b2);           // b2 = v2c_4
    bp_seed<<<seed_blocks, SEED_T>>>(llr0, b2, out, 2.f);         // out = 2*llr0 - v2c_4
    bp_check<<<chk_blocks, CBLK>>>(adj, gamma, b2, out);          // out = llr0 + v2c_5
}

// round 7
// speedup vs baseline: 1.0061x; 1.0061x over previous
#include <cuda_runtime.h>
#include <cuda_bf16.h>
#include <cstdint>

#define N_VAR 4194304
#define M_CHK 2097152
#define DC 10
#define CBLK 256
#define ADJ_BYTES (CBLK * DC * 4)

// scratch (device globals: allocation-free)
__device__ float g_b0[N_VAR];
__device__ float g_b1[N_VAR];
__device__ float g_b2[N_VAR];

__device__ __forceinline__ uint32_t smem_u32(const void* p) {
    uint32_t a;
    asm("{ .reg .u64 t; cvta.to.shared.u64 t, %1; cvt.u32.u64 %0, t; }" : "=r"(a) : "l"(p));
    return a;
}

// seed accumulator: acc = scale*llr0 - v2c_prev  (scale = 1 mid, 2 for final/out)
// Single-wave config: 512 blocks x 512 threads, 4 float4 pairs each (MLP=8).
#define SEED_T 512
#define SEED_B 512
#define SEED_CELLS (N_VAR / 4)                   // 1048576 float4 cells
#define SEED_STRIDE (SEED_B * SEED_T)            // 262144
__global__ void __launch_bounds__(SEED_T) bp_seed(const float* __restrict__ llr0,
                                                  const float* __restrict__ v2c_prev,
                                                  float* __restrict__ acc, float scale) {
    int i = blockIdx.x * SEED_T + threadIdx.x;
    const float4* L = reinterpret_cast<const float4*>(llr0);
    const float4* P = reinterpret_cast<const float4*>(v2c_prev);
    float4* A = reinterpret_cast<float4*>(acc);

    float4 l[4], p[4];
    #pragma unroll
    for (int k = 0; k < 4; k++) l[k] = __ldcs(&L[i + k * SEED_STRIDE]);
    #pragma unroll
    for (int k = 0; k < 4; k++) p[k] = __ldcs(&P[i + k * SEED_STRIDE]);
    #pragma unroll
    for (int k = 0; k < 4; k++) {
        float4 s = make_float4(fmaf(scale, l[k].x, -p[k].x), fmaf(scale, l[k].y, -p[k].y),
                               fmaf(scale, l[k].z, -p[k].z), fmaf(scale, l[k].w, -p[k].w));
        A[i + k * SEED_STRIDE] = s;
    }
}

// check-node update: gather src (L2-only), min-sum, scatter-add into pre-seeded
// dst. adj rows staged to smem via TMA (keeps L1tex wavefronts for gathers/REDs).
__global__ void __launch_bounds__(CBLK) bp_check(const int* __restrict__ adj,
                                                 const float* __restrict__ gamma_p,
                                                 const float* __restrict__ src,
                                                 float* __restrict__ dst) {
    __shared__ __align__(16) int s_adj[CBLK * DC];
    __shared__ __align__(8) unsigned long long s_mbar;

    const int tid = threadIdx.x;
    uint32_t mbar = smem_u32(&s_mbar);
    uint32_t sdst = smem_u32(s_adj);

    if (tid == 0) {
        asm volatile("mbarrier.init.shared.b64 [%0], 1;" :: "r"(mbar) : "memory");
    }
    __syncthreads();
    if (tid == 0) {
        asm volatile("mbarrier.arrive.expect_tx.shared.b64 _, [%0], %1;"
                     :: "r"(mbar), "r"((uint32_t)ADJ_BYTES) : "memory");
        const int* gsrc = adj + (size_t)blockIdx.x * (CBLK * DC);
        asm volatile(
            "cp.async.bulk.shared::cta.global.mbarrier::complete_tx::bytes "
            "[%0], [%1], %2, [%3];"
            :: "r"(sdst), "l"(gsrc), "r"((uint32_t)ADJ_BYTES), "r"(mbar) : "memory");
    }

    // overlap scalar loads with the TMA fetch
    const float gamma = __ldg(gamma_p);
    const float vlast = __ldg(&src[N_VAR - 1]);  // all padded (-1) slots wrap here

    // wait for TMA completion (phase 0)
    {
        uint32_t done;
        asm volatile(
            "{\n\t.reg .pred p;\n\t"
            "mbarrier.try_wait.parity.acquire.cta.shared::cta.b64 p, [%1], 0;\n\t"
            "selp.b32 %0, 1, 0, p;\n\t}"
            : "=r"(done) : "r"(mbar) : "memory");
        while (!done) {
            asm volatile(
                "{\n\t.reg .pred p;\n\t"
                "mbarrier.try_wait.parity.acquire.cta.shared::cta.b64 p, [%1], 0, 0x989680;\n\t"
                "selp.b32 %0, 1, 0, p;\n\t}"
                : "=r"(done) : "r"(mbar) : "memory");
        }
    }

    int idx[DC];
    #pragma unroll
    for (int j = 0; j < DC; j++) idx[j] = s_adj[tid * DC + j];

    float mag = __int_as_float(0x7f800000);  // +inf
    unsigned sgn = 0u;
    #pragma unroll
    for (int j = 0; j < DC; j++) {
        float v = (idx[j] >= 0) ? __ldcg(&src[idx[j]]) : vlast;
        sgn ^= (__float_as_uint(v + 1e-12f) & 0x80000000u);
        mag = fminf(mag, fabsf(v));
    }
    float c2v = __uint_as_float(__float_as_uint(gamma * mag) ^ sgn);

    #pragma unroll
    for (int j = 0; j < DC; j++) {
        if (idx[j] >= 0) atomicAdd(&dst[idx[j]], c2v);
    }
}

extern "C" void kernel_launch(void* const* d_in, const int* in_sizes, int n_in,
                              void* d_out, int out_size) {
    const float* llr0  = (const float*)d_in[0];
    const float* gamma = (const float*)d_in[1];
    const int*   adj   = (const int*)d_in[2];
    float* out = (float*)d_out;

    float *b0, *b1, *b2;
    cudaGetSymbolAddress((void**)&b0, g_b0);
    cudaGetSymbolAddress((void**)&b1, g_b1);
    cudaGetSymbolAddress((void**)&b2, g_b2);

    const int chk_blocks = M_CHK / CBLK;

    // n_iter = 5. Iter 1 is exact identity (v2c1 = llr0). Remaining 4 rounds:
    // accumulators pre-seeded with (llr0 - v2c_prev) so check's atomics produce
    // v2c_next in place; final accumulator is d_out seeded with (2*llr0 - v2c_4).
    cudaMemsetAsync(b0, 0, (size_t)N_VAR * sizeof(float));        // seed iter2: 0
    bp_check<<<chk_blocks, CBLK>>>(adj, gamma, llr0, b0);         // b0 = v2c_2
    bp_seed<<<SEED_B, SEED_T>>>(llr0, b0, b1, 1.f);               // b1 = llr0 - v2c_2
    bp_check<<<chk_blocks, CBLK>>>(adj, gamma, b0, b1);           // b1 = v2c_3
    bp_seed<<<SEED_B, SEED_T>>>(llr0, b1, b2, 1.f);               // b2 = llr0 - v2c_3
    bp_check<<<chk_blocks, CBLK>>>(adj, gamma, b1, b2);           // b2 = v2c_4
    bp_seed<<<SEED_B, SEED_T>>>(llr0, b2, out, 2.f);              // out = 2*llr0 - v2c_4
    bp_check<<<chk_blocks, CBLK>>>(adj, gamma, b2, out);          // out = llr0 + v2c_5
}